// round 10
// baseline (speedup 1.0000x reference)
#include <cuda_runtime.h>

#define NN 100000
#define EMAX 1600000
#define SCAN_B 1024
#define SCAN_NB ((NN + SCAN_B - 1) / SCAN_B)   // 98

// ---- scratch (device globals; no runtime allocation allowed) ----
__device__ int      g_deg[NN];
__device__ int      g_off[NN + 1];
__device__ int      g_cur[NN];
__device__ int      g_csr[EMAX + NN];   // src node per CSR slot (sorted by dst)
__device__ float    g_h [NN * 64];      // transformed features for current layer
__device__ float    g_fa[NN * 64];      // ping
__device__ float    g_fb[NN * 64];      // pong
__device__ float    g_es[NN * 4];       // per-node source attention logits
__device__ float    g_ed[NN * 4];       // per-node dest attention logits
__device__ unsigned g_gmax[12];         // per-layer per-head global max of es
__device__ int      g_bsum[SCAN_NB];
__device__ int      g_boff[SCAN_NB];

__device__ __forceinline__ unsigned fenc(float f) {
    unsigned u = __float_as_uint(f);
    return u ^ ((u & 0x80000000u) ? 0xFFFFFFFFu : 0x80000000u);
}
__device__ __forceinline__ float fdec(unsigned e) {
    unsigned u = e ^ ((e & 0x80000000u) ? 0x80000000u : 0xFFFFFFFFu);
    return __uint_as_float(u);
}
__device__ __forceinline__ float leaky02(float e) {
    return (e > 0.f) ? e : 0.2f * e;
}

// ------------------------------------------------------------------
// CSR construction
// ------------------------------------------------------------------
__global__ void k_init_deg() {
    int i = blockIdx.x * blockDim.x + threadIdx.x;
    if (i < NN) g_deg[i] = 1;           // self-loop
    if (i < 12) g_gmax[i] = 0u;
}

__global__ void k_hist(const int* __restrict__ dst, int E) {
    int i = blockIdx.x * blockDim.x + threadIdx.x;
    if (i < E) atomicAdd(&g_deg[dst[i]], 1);
}

__global__ void k_scan1() {
    __shared__ int red[8];
    int b = blockIdx.x, t = threadIdx.x;
    int s = 0;
    #pragma unroll
    for (int j = 0; j < 4; j++) {
        int idx = b * SCAN_B + j * 256 + t;
        if (idx < NN) s += g_deg[idx];
    }
    #pragma unroll
    for (int o = 16; o >= 1; o >>= 1) s += __shfl_down_sync(0xffffffffu, s, o);
    if ((t & 31) == 0) red[t >> 5] = s;
    __syncthreads();
    if (t == 0) {
        int tot = 0;
        #pragma unroll
        for (int w = 0; w < 8; w++) tot += red[w];
        g_bsum[b] = tot;
    }
}

__global__ void k_scan2() {
    __shared__ int sh[128];
    int t = threadIdx.x;
    sh[t] = (t < SCAN_NB) ? g_bsum[t] : 0;
    __syncthreads();
    for (int o = 1; o < 128; o <<= 1) {
        int v = (t >= o) ? sh[t - o] : 0;
        __syncthreads();
        sh[t] += v;
        __syncthreads();
    }
    if (t < SCAN_NB) g_boff[t] = (t == 0) ? 0 : sh[t - 1];
    if (t == SCAN_NB - 1) g_off[NN] = sh[t];
}

__global__ void k_scan3() {
    __shared__ int sh[SCAN_B];
    int b = blockIdx.x, t = threadIdx.x;
    int i = b * SCAN_B + t;
    int v = (i < NN) ? g_deg[i] : 0;
    sh[t] = v;
    __syncthreads();
    for (int o = 1; o < SCAN_B; o <<= 1) {
        int u = (t >= o) ? sh[t - o] : 0;
        __syncthreads();
        sh[t] += u;
        __syncthreads();
    }
    if (i < NN) {
        int ex = sh[t] - v + g_boff[b];
        g_off[i] = ex;
        g_cur[i] = ex;
    }
}

__global__ void k_fill(const int* __restrict__ src, const int* __restrict__ dst, int E) {
    int i = blockIdx.x * blockDim.x + threadIdx.x;
    int tot = E + NN;
    if (i >= tot) return;
    int s, d;
    if (i < E) { s = src[i]; d = dst[i]; }
    else       { s = i - E; d = s; }
    int p = atomicAdd(&g_cur[d], 1);
    g_csr[p] = s;
}

// ------------------------------------------------------------------
// Node transform: 4 nodes per warp, hoisted W smem loads.
// xin_sel: 0 -> external ptr (Fin=1), 1 -> g_fa, 2 -> g_fb
// ------------------------------------------------------------------
__global__ __launch_bounds__(256) void k_transform(
    const float* __restrict__ xext, int xin_sel, int Fin,
    const float* __restrict__ Wg,
    const float* __restrict__ avs,
    const float* __restrict__ avd,
    int layer)
{
    __shared__ float Ws[64 * 64];
    __shared__ float As[64], Ad[64];
    __shared__ unsigned bmax[4];
    const float* xin = (xin_sel == 0) ? xext : (xin_sel == 1 ? g_fa : g_fb);
    int t = threadIdx.x;
    for (int i = t; i < Fin * 64; i += blockDim.x) Ws[i] = Wg[i];
    if (t < 64) { As[t] = avs[t]; Ad[t] = avd[t]; }
    if (t < 4)  bmax[t] = 0u;
    __syncthreads();

    int lane = t & 31;
    int c0   = lane * 2;
    int n0 = blockIdx.x * 32 + (t >> 5) * 4;
    int nv = NN - n0; if (nv > 4) nv = 4;

    float acc[4][2];
    #pragma unroll
    for (int r = 0; r < 4; r++) { acc[r][0] = 0.f; acc[r][1] = 0.f; }

    if (Fin == 1) {
        #pragma unroll
        for (int r = 0; r < 4; r++) {
            if (r < nv) {
                float xv = __ldg(xin + n0 + r);
                acc[r][0] = xv * Ws[c0];
                acc[r][1] = xv * Ws[c0 + 1];
            }
        }
    } else {
        const float* x0p = xin + (size_t)n0 * 64;
        #pragma unroll
        for (int k = 0; k < 64; k += 4) {
            float2 w0 = *(const float2*)(Ws + (k + 0) * 64 + c0);
            float2 w1 = *(const float2*)(Ws + (k + 1) * 64 + c0);
            float2 w2 = *(const float2*)(Ws + (k + 2) * 64 + c0);
            float2 w3 = *(const float2*)(Ws + (k + 3) * 64 + c0);
            #pragma unroll
            for (int r = 0; r < 4; r++) {
                if (r < nv) {
                    float4 xv = __ldg((const float4*)(x0p + r * 64 + k));
                    acc[r][0] += xv.x * w0.x; acc[r][1] += xv.x * w0.y;
                    acc[r][0] += xv.y * w1.x; acc[r][1] += xv.y * w1.y;
                    acc[r][0] += xv.z * w2.x; acc[r][1] += xv.z * w2.y;
                    acc[r][0] += xv.w * w3.x; acc[r][1] += xv.w * w3.y;
                }
            }
        }
    }

    #pragma unroll
    for (int r = 0; r < 4; r++) {
        if (r >= nv) break;
        int n = n0 + r;
        float a0 = acc[r][0], a1 = acc[r][1];
        size_t base = (size_t)n * 64 + c0;
        g_h[base]     = a0;
        g_h[base + 1] = a1;
        float ps = a0 * As[c0] + a1 * As[c0 + 1];
        float pd = a0 * Ad[c0] + a1 * Ad[c0 + 1];
        #pragma unroll
        for (int o = 4; o >= 1; o >>= 1) {
            ps += __shfl_down_sync(0xffffffffu, ps, o);
            pd += __shfl_down_sync(0xffffffffu, pd, o);
        }
        if ((lane & 7) == 0) {
            int hd = lane >> 3;
            g_es[n * 4 + hd] = ps;
            g_ed[n * 4 + hd] = pd;
            atomicMax(&bmax[hd], fenc(ps));
        }
    }
    __syncthreads();
    if (t < 4) atomicMax(&g_gmax[layer * 4 + t], bmax[t]);
}

// ------------------------------------------------------------------
// Half-warp (16-lane) single-pass softmax aggregation.
// Edge weights computed ONCE per (edge, head): lane l owns edge
// base+l, loads es as float4, computes 4 exps, stages to smem;
// the accumulate loop reads weights via conflict-free LDS broadcast.
// swt: per-half-warp 80-float region (16 edges x 4 heads, 16B-aligned).
// ------------------------------------------------------------------
__device__ __forceinline__ float4 agg_node16(
    int n, int l16, int hb, unsigned hmask, int layer,
    const float* __restrict__ bias, float* __restrict__ swt)
{
    int hd = l16 >> 2;
    int q0 = l16 * 4;
    int beg = __ldg(&g_off[n]), end = __ldg(&g_off[n + 1]);
    float4 edv4 = __ldg((const float4*)(g_ed + (size_t)n * 4));
    float m0 = leaky02(fdec(g_gmax[layer * 4 + 0]) + edv4.x);
    float m1 = leaky02(fdec(g_gmax[layer * 4 + 1]) + edv4.y);
    float m2 = leaky02(fdec(g_gmax[layer * 4 + 2]) + edv4.z);
    float m3 = leaky02(fdec(g_gmax[layer * 4 + 3]) + edv4.w);

    float s = 0.f;
    float a0 = 0.f, a1 = 0.f, a2 = 0.f, a3 = 0.f;
    for (int base = beg; base < end; base += 16) {
        int rem = end - base;
        int cnt = rem < 16 ? rem : 16;
        int safel = l16 < rem ? l16 : 0;
        int myidx = __ldg(&g_csr[base + safel]);   // coalesced, 16 edges
        // 4 exps for MY edge (one per head) -- minimum possible
        float4 ev = __ldg((const float4*)(g_es + (size_t)myidx * 4));
        float4 w4;
        w4.x = __expf(leaky02(ev.x + edv4.x) - m0);
        w4.y = __expf(leaky02(ev.y + edv4.y) - m1);
        w4.z = __expf(leaky02(ev.z + edv4.z) - m2);
        w4.w = __expf(leaky02(ev.w + edv4.w) - m3);
        __syncwarp(hmask);                 // protect prior chunk's reads
        *(float4*)(swt + q0) = w4;
        __syncwarp(hmask);

        int j = 0;
        for (; j + 8 <= cnt; j += 8) {
            int sc[8]; float4 hv[8];
            #pragma unroll
            for (int q = 0; q < 8; q++)
                sc[q] = __shfl_sync(hmask, myidx, hb + j + q);
            #pragma unroll
            for (int q = 0; q < 8; q++)
                hv[q] = __ldg((const float4*)(g_h + (size_t)sc[q] * 64 + q0));
            #pragma unroll
            for (int q = 0; q < 8; q++) {
                float w = swt[(j + q) * 4 + hd];
                s  += w;
                a0 += w * hv[q].x; a1 += w * hv[q].y;
                a2 += w * hv[q].z; a3 += w * hv[q].w;
            }
        }
        if (j + 4 <= cnt) {
            int sc[4]; float4 hv[4];
            #pragma unroll
            for (int q = 0; q < 4; q++)
                sc[q] = __shfl_sync(hmask, myidx, hb + j + q);
            #pragma unroll
            for (int q = 0; q < 4; q++)
                hv[q] = __ldg((const float4*)(g_h + (size_t)sc[q] * 64 + q0));
            #pragma unroll
            for (int q = 0; q < 4; q++) {
                float w = swt[(j + q) * 4 + hd];
                s  += w;
                a0 += w * hv[q].x; a1 += w * hv[q].y;
                a2 += w * hv[q].z; a3 += w * hv[q].w;
            }
            j += 4;
        }
        for (; j < cnt; j++) {
            int sc = __shfl_sync(hmask, myidx, hb + j);
            float4 hv = __ldg((const float4*)(g_h + (size_t)sc * 64 + q0));
            float w = swt[j * 4 + hd];
            s  += w;
            a0 += w * hv.x; a1 += w * hv.y;
            a2 += w * hv.z; a3 += w * hv.w;
        }
    }
    float inv = 1.f / (s + 1e-16f);
    float4 bv = __ldg((const float4*)(bias + q0));
    float4 o;
    o.x = a0 * inv + bv.x;
    o.y = a1 * inv + bv.y;
    o.z = a2 * inv + bv.z;
    o.w = a3 * inv + bv.w;
    return o;
}

// ------------------------------------------------------------------
// Aggregation -> feature buffer (layers 0 and 1): half-warp per node
// ------------------------------------------------------------------
__global__ __launch_bounds__(256) void k_aggregate(
    const float* __restrict__ bias, int out_sel, int layer)
{
    __shared__ float swts[16][80];      // stride 80: 16B-aligned, bank-split halves
    float* xout = (out_sel == 1) ? g_fa : g_fb;
    int t    = threadIdx.x;
    int lane = t & 31;
    int l16  = lane & 15;
    int hb   = lane & 16;
    unsigned hmask = 0xFFFFu << hb;
    int n = blockIdx.x * 16 + (t >> 4);
    if (n >= NN) return;
    float4 o = agg_node16(n, l16, hb, hmask, layer, bias, swts[t >> 4]);
    *(float4*)(xout + (size_t)n * 64 + l16 * 4) = o;
}

// ------------------------------------------------------------------
// Layer-2 aggregate fused with MLP + decoder + softmax.
// Half-warp per node: 16 nodes per 256-thread block.
// ------------------------------------------------------------------
__global__ __launch_bounds__(256) void k_agg_mlp(
    const float* __restrict__ bias, int layer,
    const float* __restrict__ lw1, const float* __restrict__ lb1,
    const float* __restrict__ lw2, const float* __restrict__ lb2,
    const float* __restrict__ dw,  const float* __restrict__ db,
    float* __restrict__ out)
{
    __shared__ float W1s[64 * 64];
    __shared__ float W2s[64 * 16];
    __shared__ float b1s[64], b2s[16], dws[64], dbs[4];
    __shared__ float t1s[16][68];
    __shared__ float t2s[16][16];
    __shared__ float lgs[16][4];
    __shared__ float swts[16][80];
    int t = threadIdx.x;
    for (int i = t; i < 64 * 64; i += blockDim.x) W1s[i] = lw1[i];
    for (int i = t; i < 64 * 16; i += blockDim.x) W2s[i] = lw2[i];
    if (t < 64) b1s[t] = lb1[t];
    if (t < 16) b2s[t] = lb2[t];
    if (t < 64) dws[t] = dw[t];
    if (t < 4)  dbs[t] = db[t];
    __syncthreads();

    int lane = t & 31;
    int l16  = lane & 15;
    int hb   = lane & 16;
    unsigned hmask = 0xFFFFu << hb;
    int hid  = t >> 4;                  // half-warp id within block (0..15)
    int q0   = l16 * 4;
    int n = blockIdx.x * 16 + hid;
    if (n >= NN) return;

    // ---- layer-2 aggregation (half-warp) ----
    float4 xr = agg_node16(n, l16, hb, hmask, layer, bias, swts[hid]);
    *(float4*)(&t1s[hid][q0]) = xr;
    __syncwarp();

    // ---- Linear(64,64) + ReLU: lane owns 4 output channels ----
    float a0 = b1s[q0], a1 = b1s[q0 + 1], a2 = b1s[q0 + 2], a3 = b1s[q0 + 3];
    #pragma unroll
    for (int k = 0; k < 64; k++) {
        float xv = t1s[hid][k];
        float4 wv = *(const float4*)(W1s + k * 64 + q0);
        a0 += xv * wv.x; a1 += xv * wv.y;
        a2 += xv * wv.z; a3 += xv * wv.w;
    }
    a0 = a0 > 0.f ? a0 : 0.f;
    a1 = a1 > 0.f ? a1 : 0.f;
    a2 = a2 > 0.f ? a2 : 0.f;
    a3 = a3 > 0.f ? a3 : 0.f;
    __syncwarp();
    t1s[hid][q0]     = a0;
    t1s[hid][q0 + 1] = a1;
    t1s[hid][q0 + 2] = a2;
    t1s[hid][q0 + 3] = a3;
    __syncwarp();

    // ---- Linear(64,16): lane l16 computes output channel l16 ----
    {
        float acc = b2s[l16];
        #pragma unroll
        for (int k = 0; k < 64; k++) acc += t1s[hid][k] * W2s[k * 16 + l16];
        t2s[hid][l16] = acc;
    }
    __syncwarp();

    // ---- decoder Linear(16,4) ----
    if (l16 < 4) {
        float lg = dbs[l16];
        #pragma unroll
        for (int i = 0; i < 16; i++) lg += t2s[hid][i] * dws[i * 4 + l16];
        lgs[hid][l16] = lg;
    }
    __syncwarp();

    // ---- softmax over 4 logits ----
    if (l16 < 4) {
        float l0 = lgs[hid][0], l1 = lgs[hid][1], l2 = lgs[hid][2], l3 = lgs[hid][3];
        float mx = fmaxf(fmaxf(l0, l1), fmaxf(l2, l3));
        float e0 = __expf(l0 - mx), e1 = __expf(l1 - mx);
        float e2 = __expf(l2 - mx), e3 = __expf(l3 - mx);
        float den = e0 + e1 + e2 + e3;
        float mine = (l16 == 0) ? e0 : (l16 == 1) ? e1 : (l16 == 2) ? e2 : e3;
        out[(size_t)n * 4 + l16] = mine / den;
    }
}

// ------------------------------------------------------------------
extern "C" void kernel_launch(void* const* d_in, const int* in_sizes, int n_in,
                              void* d_out, int out_size)
{
    const float* x   = (const float*)d_in[0];
    const int*   ei  = (const int*)  d_in[1];
    int E = in_sizes[1] / 2;
    const int* src = ei;
    const int* dst = ei + E;
    const float* W0  = (const float*)d_in[2];
    const float* as0 = (const float*)d_in[3];
    const float* ad0 = (const float*)d_in[4];
    const float* b0  = (const float*)d_in[5];
    const float* W1  = (const float*)d_in[6];
    const float* as1 = (const float*)d_in[7];
    const float* ad1 = (const float*)d_in[8];
    const float* b1  = (const float*)d_in[9];
    const float* W2  = (const float*)d_in[10];
    const float* as2 = (const float*)d_in[11];
    const float* ad2 = (const float*)d_in[12];
    const float* b2  = (const float*)d_in[13];
    const float* lw1 = (const float*)d_in[14];
    const float* lb1 = (const float*)d_in[15];
    const float* lw2 = (const float*)d_in[16];
    const float* lb2 = (const float*)d_in[17];
    const float* dw  = (const float*)d_in[18];
    const float* db  = (const float*)d_in[19];
    float* out = (float*)d_out;

    const int AGG16_BLOCKS = (NN + 15) / 16;  // half-warp per node
    const int TRF_BLOCKS   = (NN + 31) / 32;  // 4 nodes/warp, 8 warps/block
    const int NT = 256;

    // CSR build (reused across all 3 GAT layers)
    k_init_deg<<<(NN + 255) / 256, 256>>>();
    k_hist<<<(E + 255) / 256, 256>>>(dst, E);
    k_scan1<<<SCAN_NB, 256>>>();
    k_scan2<<<1, 128>>>();
    k_scan3<<<SCAN_NB, SCAN_B>>>();
    k_fill<<<(E + NN + 255) / 256, 256>>>(src, dst, E);

    // GAT layer 0 (Fin=1): out -> g_fa
    k_transform<<<TRF_BLOCKS, NT>>>(x, 0, 1, W0, as0, ad0, 0);
    k_aggregate<<<AGG16_BLOCKS, NT>>>(b0, 1, 0);
    // GAT layer 1 (Fin=64): in g_fa, out -> g_fb
    k_transform<<<TRF_BLOCKS, NT>>>(nullptr, 1, 64, W1, as1, ad1, 1);
    k_aggregate<<<AGG16_BLOCKS, NT>>>(b1, 2, 1);
    // GAT layer 2 (Fin=64): in g_fb, fused aggregate + MLP + decoder -> out
    k_transform<<<TRF_BLOCKS, NT>>>(nullptr, 2, 64, W2, as2, ad2, 2);
    k_agg_mlp<<<AGG16_BLOCKS, NT>>>(b2, 2, lw1, lb1, lw2, lb2, dw, db, out);
}

// round 11
// speedup vs baseline: 1.1301x; 1.1301x over previous
#include <cuda_runtime.h>

#define NN 100000
#define EMAX 1600000
#define SCAN_B 1024
#define SCAN_NB ((NN + SCAN_B - 1) / SCAN_B)   // 98

// ---- scratch (device globals; no runtime allocation allowed) ----
__device__ int      g_deg[NN];
__device__ int      g_off[NN + 1];
__device__ int      g_cur[NN];
__device__ int      g_csr[EMAX + NN];   // src node per CSR slot (sorted by dst)
__device__ float    g_h [NN * 64];      // transformed features for current layer
__device__ float    g_fa[NN * 64];      // ping
__device__ float    g_fb[NN * 64];      // pong
__device__ float    g_es[NN * 4];       // per-node source attention logits
__device__ float    g_ed[NN * 4];       // per-node dest attention logits
__device__ unsigned g_gmax[12];         // per-layer per-head global max of es
__device__ int      g_bsum[SCAN_NB];

__device__ __forceinline__ unsigned fenc(float f) {
    unsigned u = __float_as_uint(f);
    return u ^ ((u & 0x80000000u) ? 0xFFFFFFFFu : 0x80000000u);
}
__device__ __forceinline__ float fdec(unsigned e) {
    unsigned u = e ^ ((e & 0x80000000u) ? 0x80000000u : 0xFFFFFFFFu);
    return __uint_as_float(u);
}
__device__ __forceinline__ float leaky02(float e) {
    return (e > 0.f) ? e : 0.2f * e;
}

// ------------------------------------------------------------------
// CSR construction
// ------------------------------------------------------------------
__global__ void k_init_deg() {
    int i = blockIdx.x * blockDim.x + threadIdx.x;
    if (i < NN) g_deg[i] = 1;           // self-loop
    if (i < 12) g_gmax[i] = 0u;
}

__global__ void k_hist(const int* __restrict__ dst, int E) {
    int i = blockIdx.x * blockDim.x + threadIdx.x;
    if (i < E) atomicAdd(&g_deg[dst[i]], 1);
}

__global__ void k_scan1() {
    __shared__ int red[8];
    int b = blockIdx.x, t = threadIdx.x;
    int s = 0;
    #pragma unroll
    for (int j = 0; j < 4; j++) {
        int idx = b * SCAN_B + j * 256 + t;
        if (idx < NN) s += g_deg[idx];
    }
    #pragma unroll
    for (int o = 16; o >= 1; o >>= 1) s += __shfl_down_sync(0xffffffffu, s, o);
    if ((t & 31) == 0) red[t >> 5] = s;
    __syncthreads();
    if (t == 0) {
        int tot = 0;
        #pragma unroll
        for (int w = 0; w < 8; w++) tot += red[w];
        g_bsum[b] = tot;
    }
}

// scan3: each block computes its own offset from g_bsum (no scan2 kernel),
// does local inclusive scan, writes off/cur, AND plants the self-loop.
__global__ void k_scan3() {
    __shared__ int sh[SCAN_B];
    __shared__ int redsum[32];
    __shared__ int s_bo;
    int b = blockIdx.x, t = threadIdx.x;

    // block offset = sum of g_bsum[0..b)
    {
        int v = (t < SCAN_NB && t < b) ? g_bsum[t] : 0;
        #pragma unroll
        for (int o = 16; o >= 1; o >>= 1) v += __shfl_down_sync(0xffffffffu, v, o);
        if ((t & 31) == 0) redsum[t >> 5] = v;
        __syncthreads();
        if (t == 0) {
            int s = 0;
            #pragma unroll
            for (int w = 0; w < 32; w++) s += redsum[w];
            s_bo = s;
        }
        __syncthreads();
    }
    int bo = s_bo;

    int i = b * SCAN_B + t;
    int v = (i < NN) ? g_deg[i] : 0;
    sh[t] = v;
    __syncthreads();
    for (int o = 1; o < SCAN_B; o <<= 1) {
        int u = (t >= o) ? sh[t - o] : 0;
        __syncthreads();
        sh[t] += u;
        __syncthreads();
    }
    if (i < NN) {
        int ex = sh[t] - v + bo;
        g_off[i] = ex;
        g_csr[ex] = i;          // self-loop occupies first slot
        g_cur[i] = ex + 1;      // edges fill after it
    }
    if (b == SCAN_NB - 1 && t == SCAN_B - 1)
        g_off[NN] = bo + sh[SCAN_B - 1];
}

__global__ void k_fill(const int* __restrict__ src, const int* __restrict__ dst, int E) {
    int i = blockIdx.x * blockDim.x + threadIdx.x;
    if (i >= E) return;
    int s = src[i], d = dst[i];
    int p = atomicAdd(&g_cur[d], 1);
    g_csr[p] = s;
}

// ------------------------------------------------------------------
// Node transform: 4 nodes per warp, hoisted W smem loads.
// xin_sel: 0 -> external ptr (Fin=1), 1 -> g_fa, 2 -> g_fb
// ------------------------------------------------------------------
__global__ __launch_bounds__(256) void k_transform(
    const float* __restrict__ xext, int xin_sel, int Fin,
    const float* __restrict__ Wg,
    const float* __restrict__ avs,
    const float* __restrict__ avd,
    int layer)
{
    __shared__ float Ws[64 * 64];
    __shared__ float As[64], Ad[64];
    __shared__ unsigned bmax[4];
    const float* xin = (xin_sel == 0) ? xext : (xin_sel == 1 ? g_fa : g_fb);
    int t = threadIdx.x;
    {   // vectorized weight staging
        const float4* W4 = (const float4*)Wg;
        float4* Ws4 = (float4*)Ws;
        for (int i = t; i < Fin * 16; i += blockDim.x) Ws4[i] = __ldg(W4 + i);
    }
    if (t < 64) { As[t] = avs[t]; Ad[t] = avd[t]; }
    if (t < 4)  bmax[t] = 0u;
    __syncthreads();

    int lane = t & 31;
    int c0   = lane * 2;
    int n0 = blockIdx.x * 32 + (t >> 5) * 4;
    int nv = NN - n0; if (nv > 4) nv = 4;

    float acc[4][2];
    #pragma unroll
    for (int r = 0; r < 4; r++) { acc[r][0] = 0.f; acc[r][1] = 0.f; }

    if (Fin == 1) {
        #pragma unroll
        for (int r = 0; r < 4; r++) {
            if (r < nv) {
                float xv = __ldg(xin + n0 + r);
                acc[r][0] = xv * Ws[c0];
                acc[r][1] = xv * Ws[c0 + 1];
            }
        }
    } else {
        const float* x0p = xin + (size_t)n0 * 64;
        #pragma unroll
        for (int k = 0; k < 64; k += 4) {
            float2 w0 = *(const float2*)(Ws + (k + 0) * 64 + c0);
            float2 w1 = *(const float2*)(Ws + (k + 1) * 64 + c0);
            float2 w2 = *(const float2*)(Ws + (k + 2) * 64 + c0);
            float2 w3 = *(const float2*)(Ws + (k + 3) * 64 + c0);
            #pragma unroll
            for (int r = 0; r < 4; r++) {
                if (r < nv) {
                    float4 xv = __ldg((const float4*)(x0p + r * 64 + k));
                    acc[r][0] += xv.x * w0.x; acc[r][1] += xv.x * w0.y;
                    acc[r][0] += xv.y * w1.x; acc[r][1] += xv.y * w1.y;
                    acc[r][0] += xv.z * w2.x; acc[r][1] += xv.z * w2.y;
                    acc[r][0] += xv.w * w3.x; acc[r][1] += xv.w * w3.y;
                }
            }
        }
    }

    #pragma unroll
    for (int r = 0; r < 4; r++) {
        if (r >= nv) break;
        int n = n0 + r;
        float a0 = acc[r][0], a1 = acc[r][1];
        float2 hv2; hv2.x = a0; hv2.y = a1;
        *(float2*)(g_h + (size_t)n * 64 + c0) = hv2;
        float ps = a0 * As[c0] + a1 * As[c0 + 1];
        float pd = a0 * Ad[c0] + a1 * Ad[c0 + 1];
        #pragma unroll
        for (int o = 4; o >= 1; o >>= 1) {
            ps += __shfl_down_sync(0xffffffffu, ps, o);
            pd += __shfl_down_sync(0xffffffffu, pd, o);
        }
        if ((lane & 7) == 0) {
            int hd = lane >> 3;
            g_es[n * 4 + hd] = ps;
            g_ed[n * 4 + hd] = pd;
            atomicMax(&bmax[hd], fenc(ps));
        }
    }
    __syncthreads();
    if (t < 4) atomicMax(&g_gmax[layer * 4 + t], bmax[t]);
}

// ------------------------------------------------------------------
// Half-warp (16-lane) single-pass softmax aggregation (R9-proven).
// Lane l owns channels 4l..4l+3 (float4 row loads), head = l>>2.
// ------------------------------------------------------------------
__device__ __forceinline__ float4 agg_node16(
    int n, int l16, int hb, unsigned hmask, int layer,
    const float* __restrict__ bias)
{
    int hd = l16 >> 2;
    int q0 = l16 * 4;
    int beg = __ldg(&g_off[n]), end = __ldg(&g_off[n + 1]);
    float edv = __ldg(&g_ed[n * 4 + hd]);
    float m = leaky02(fdec(g_gmax[layer * 4 + hd]) + edv);

    float s = 0.f;
    float a0 = 0.f, a1 = 0.f, a2 = 0.f, a3 = 0.f;
    for (int base = beg; base < end; base += 16) {
        int rem = end - base;
        int cnt = rem < 16 ? rem : 16;
        int safel = l16 < rem ? l16 : 0;
        int myidx = __ldg(&g_csr[base + safel]);   // coalesced 64B, 16 edges
        int j = 0;
        for (; j + 8 <= cnt; j += 8) {
            int sc[8]; float ev[8]; float4 hv[8];
            #pragma unroll
            for (int q = 0; q < 8; q++)
                sc[q] = __shfl_sync(hmask, myidx, hb + j + q);
            #pragma unroll
            for (int q = 0; q < 8; q++) {
                ev[q] = __ldg(&g_es[sc[q] * 4 + hd]);
                hv[q] = __ldg((const float4*)(g_h + (size_t)sc[q] * 64 + q0));
            }
            #pragma unroll
            for (int q = 0; q < 8; q++) {
                float w = __expf(leaky02(ev[q] + edv) - m);
                s  += w;
                a0 += w * hv[q].x; a1 += w * hv[q].y;
                a2 += w * hv[q].z; a3 += w * hv[q].w;
            }
        }
        if (j + 4 <= cnt) {
            int sc[4]; float ev[4]; float4 hv[4];
            #pragma unroll
            for (int q = 0; q < 4; q++)
                sc[q] = __shfl_sync(hmask, myidx, hb + j + q);
            #pragma unroll
            for (int q = 0; q < 4; q++) {
                ev[q] = __ldg(&g_es[sc[q] * 4 + hd]);
                hv[q] = __ldg((const float4*)(g_h + (size_t)sc[q] * 64 + q0));
            }
            #pragma unroll
            for (int q = 0; q < 4; q++) {
                float w = __expf(leaky02(ev[q] + edv) - m);
                s  += w;
                a0 += w * hv[q].x; a1 += w * hv[q].y;
                a2 += w * hv[q].z; a3 += w * hv[q].w;
            }
            j += 4;
        }
        for (; j < cnt; j++) {
            int sc = __shfl_sync(hmask, myidx, hb + j);
            float  e  = __ldg(&g_es[sc * 4 + hd]);
            float4 hv = __ldg((const float4*)(g_h + (size_t)sc * 64 + q0));
            float w = __expf(leaky02(e + edv) - m);
            s  += w;
            a0 += w * hv.x; a1 += w * hv.y;
            a2 += w * hv.z; a3 += w * hv.w;
        }
    }
    float inv = 1.f / (s + 1e-16f);
    float4 bv = __ldg((const float4*)(bias + q0));
    float4 o;
    o.x = a0 * inv + bv.x;
    o.y = a1 * inv + bv.y;
    o.z = a2 * inv + bv.z;
    o.w = a3 * inv + bv.w;
    return o;
}

// ------------------------------------------------------------------
// Aggregation -> feature buffer (layers 0 and 1): half-warp per node
// ------------------------------------------------------------------
__global__ __launch_bounds__(256) void k_aggregate(
    const float* __restrict__ bias, int out_sel, int layer)
{
    float* xout = (out_sel == 1) ? g_fa : g_fb;
    int t    = threadIdx.x;
    int lane = t & 31;
    int l16  = lane & 15;
    int hb   = lane & 16;
    unsigned hmask = 0xFFFFu << hb;
    int n = blockIdx.x * 16 + (t >> 4);
    if (n >= NN) return;
    float4 o = agg_node16(n, l16, hb, hmask, layer, bias);
    *(float4*)(xout + (size_t)n * 64 + l16 * 4) = o;
}

// ------------------------------------------------------------------
// Layer-2 aggregate fused with MLP + decoder + softmax.
// Half-warp per node: 16 nodes per 256-thread block (R9-proven).
// ------------------------------------------------------------------
__global__ __launch_bounds__(256) void k_agg_mlp(
    const float* __restrict__ bias, int layer,
    const float* __restrict__ lw1, const float* __restrict__ lb1,
    const float* __restrict__ lw2, const float* __restrict__ lb2,
    const float* __restrict__ dw,  const float* __restrict__ db,
    float* __restrict__ out)
{
    __shared__ float W1s[64 * 64];
    __shared__ float W2s[64 * 16];
    __shared__ float b1s[64], b2s[16], dws[64], dbs[4];
    __shared__ float t1s[16][68];
    __shared__ float t2s[16][16];
    __shared__ float lgs[16][4];
    int t = threadIdx.x;
    {
        const float4* W14 = (const float4*)lw1;
        float4* W1s4 = (float4*)W1s;
        for (int i = t; i < 64 * 16; i += blockDim.x) W1s4[i] = __ldg(W14 + i);
        const float4* W24 = (const float4*)lw2;
        float4* W2s4 = (float4*)W2s;
        for (int i = t; i < 16 * 16; i += blockDim.x) W2s4[i] = __ldg(W24 + i);
    }
    if (t < 64) b1s[t] = lb1[t];
    if (t < 16) b2s[t] = lb2[t];
    if (t < 64) dws[t] = dw[t];
    if (t < 4)  dbs[t] = db[t];
    __syncthreads();

    int lane = t & 31;
    int l16  = lane & 15;
    int hb   = lane & 16;
    unsigned hmask = 0xFFFFu << hb;
    int hid  = t >> 4;                  // half-warp id within block (0..15)
    int q0   = l16 * 4;
    int n = blockIdx.x * 16 + hid;
    if (n >= NN) return;

    // ---- layer-2 aggregation (half-warp) ----
    float4 xr = agg_node16(n, l16, hb, hmask, layer, bias);
    *(float4*)(&t1s[hid][q0]) = xr;
    __syncwarp();

    // ---- Linear(64,64) + ReLU: lane owns 4 output channels ----
    float a0 = b1s[q0], a1 = b1s[q0 + 1], a2 = b1s[q0 + 2], a3 = b1s[q0 + 3];
    #pragma unroll
    for (int k = 0; k < 64; k++) {
        float xv = t1s[hid][k];
        float4 wv = *(const float4*)(W1s + k * 64 + q0);
        a0 += xv * wv.x; a1 += xv * wv.y;
        a2 += xv * wv.z; a3 += xv * wv.w;
    }
    a0 = a0 > 0.f ? a0 : 0.f;
    a1 = a1 > 0.f ? a1 : 0.f;
    a2 = a2 > 0.f ? a2 : 0.f;
    a3 = a3 > 0.f ? a3 : 0.f;
    __syncwarp();
    t1s[hid][q0]     = a0;
    t1s[hid][q0 + 1] = a1;
    t1s[hid][q0 + 2] = a2;
    t1s[hid][q0 + 3] = a3;
    __syncwarp();

    // ---- Linear(64,16): lane l16 computes output channel l16 ----
    {
        float acc = b2s[l16];
        #pragma unroll
        for (int k = 0; k < 64; k++) acc += t1s[hid][k] * W2s[k * 16 + l16];
        t2s[hid][l16] = acc;
    }
    __syncwarp();

    // ---- decoder Linear(16,4) ----
    if (l16 < 4) {
        float lg = dbs[l16];
        #pragma unroll
        for (int i = 0; i < 16; i++) lg += t2s[hid][i] * dws[i * 4 + l16];
        lgs[hid][l16] = lg;
    }
    __syncwarp();

    // ---- softmax over 4 logits ----
    if (l16 < 4) {
        float l0 = lgs[hid][0], l1 = lgs[hid][1], l2 = lgs[hid][2], l3 = lgs[hid][3];
        float mx = fmaxf(fmaxf(l0, l1), fmaxf(l2, l3));
        float e0 = __expf(l0 - mx), e1 = __expf(l1 - mx);
        float e2 = __expf(l2 - mx), e3 = __expf(l3 - mx);
        float den = e0 + e1 + e2 + e3;
        float mine = (l16 == 0) ? e0 : (l16 == 1) ? e1 : (l16 == 2) ? e2 : e3;
        out[(size_t)n * 4 + l16] = mine / den;
    }
}

// ------------------------------------------------------------------
extern "C" void kernel_launch(void* const* d_in, const int* in_sizes, int n_in,
                              void* d_out, int out_size)
{
    const float* x   = (const float*)d_in[0];
    const int*   ei  = (const int*)  d_in[1];
    int E = in_sizes[1] / 2;
    const int* src = ei;
    const int* dst = ei + E;
    const float* W0  = (const float*)d_in[2];
    const float* as0 = (const float*)d_in[3];
    const float* ad0 = (const float*)d_in[4];
    const float* b0  = (const float*)d_in[5];
    const float* W1  = (const float*)d_in[6];
    const float* as1 = (const float*)d_in[7];
    const float* ad1 = (const float*)d_in[8];
    const float* b1  = (const float*)d_in[9];
    const float* W2  = (const float*)d_in[10];
    const float* as2 = (const float*)d_in[11];
    const float* ad2 = (const float*)d_in[12];
    const float* b2  = (const float*)d_in[13];
    const float* lw1 = (const float*)d_in[14];
    const float* lb1 = (const float*)d_in[15];
    const float* lw2 = (const float*)d_in[16];
    const float* lb2 = (const float*)d_in[17];
    const float* dw  = (const float*)d_in[18];
    const float* db  = (const float*)d_in[19];
    float* out = (float*)d_out;

    const int AGG16_BLOCKS = (NN + 15) / 16;  // half-warp per node
    const int TRF_BLOCKS   = (NN + 31) / 32;  // 4 nodes/warp, 8 warps/block
    const int NT = 256;

    // CSR build (reused across all 3 GAT layers)
    k_init_deg<<<(NN + 255) / 256, 256>>>();
    k_hist<<<(E + 255) / 256, 256>>>(dst, E);
    k_scan1<<<SCAN_NB, 256>>>();
    k_scan3<<<SCAN_NB, SCAN_B>>>();
    k_fill<<<(E + 255) / 256, 256>>>(src, dst, E);

    // GAT layer 0 (Fin=1): out -> g_fa
    k_transform<<<TRF_BLOCKS, NT>>>(x, 0, 1, W0, as0, ad0, 0);
    k_aggregate<<<AGG16_BLOCKS, NT>>>(b0, 1, 0);
    // GAT layer 1 (Fin=64): in g_fa, out -> g_fb
    k_transform<<<TRF_BLOCKS, NT>>>(nullptr, 1, 64, W1, as1, ad1, 1);
    k_aggregate<<<AGG16_BLOCKS, NT>>>(b1, 2, 1);
    // GAT layer 2 (Fin=64): in g_fb, fused aggregate + MLP + decoder -> out
    k_transform<<<TRF_BLOCKS, NT>>>(nullptr, 2, 64, W2, as2, ad2, 2);
    k_agg_mlp<<<AGG16_BLOCKS, NT>>>(b2, 2, lw1, lb1, lw2, lb2, dw, db, out);
}